// round 4
// baseline (speedup 1.0000x reference)
#include <cuda_runtime.h>
#include <math.h>

// NCA update: fused GEMM1+GEMM2 in registers, shfl-reduce.
// out = x + floor(rand+0.5) * (W2 @ relu(W1 @ perception(x) + b1))
// x[32,12,256,256], w1[96,48], b1[96], w2[12,96], rand[32,1,256,256].

#define CC   12
#define FCH  96
#define K4C  48
#define HH   256
#define WW   256
#define TPX  128
#define NT   256
#define FST  132   // padded row stride (floats)

// dynamic smem layout (float offsets)
#define OFF_XS   0                      // [12][3][132] halo (cols 0..129 used)
#define SZ_XS    (CC*3*FST)             // 4752
#define OFF_F    (OFF_XS + SZ_XS)       // [48][132] perception features
#define SZ_F     (K4C*FST)              // 6336
#define OFF_W1T  (OFF_F + SZ_F)         // [48][96]: w1T[k][o] = w1[o][k]
#define SZ_W1T   (K4C*FCH)              // 4608
#define OFF_W2T  (OFF_W1T + SZ_W1T)     // [96][12]: w2T[k][o] = w2[o][k]
#define SZ_W2T   (FCH*CC)               // 1152
#define OFF_B1   (OFF_W2T + SZ_W2T)     // [96]
#define SZ_B1    FCH
#define SMEM_FLOATS (OFF_B1 + SZ_B1)    // 16944
#define SMEM_BYTES  (SMEM_FLOATS * 4)   // 67776

__global__ __launch_bounds__(NT, 2)
void nca_kernel(const float* __restrict__ x,
                const float* __restrict__ w1,
                const float* __restrict__ b1,
                const float* __restrict__ w2,
                const float* __restrict__ rmask,
                float* __restrict__ out)
{
    extern __shared__ float sm[];
    float* XS  = sm + OFF_XS;
    float* F   = sm + OFF_F;
    float* W1T = sm + OFF_W1T;
    float* W2T = sm + OFF_W2T;
    float* B1  = sm + OFF_B1;

    const int tid = threadIdx.x;
    const int x0  = blockIdx.x * TPX;   // 0 or 128
    const int yy  = blockIdx.y;         // 0..255
    const int bb  = blockIdx.z;         // 0..31

    // ---- Phase 0: stage weights (transposed) + bias + halo ----
    for (int i = tid; i < FCH * K4C; i += NT) {
        int o = i / K4C, c = i % K4C;           // w1 row-major [96][48]
        W1T[c * FCH + o] = w1[i];
    }
    for (int i = tid; i < CC * FCH; i += NT) {
        int o = i / FCH, k = i % FCH;           // w2 row-major [12][96]
        W2T[k * CC + o] = w2[i];
    }
    if (tid < FCH) B1[tid] = b1[tid];

    const float* xb = x + (size_t)bb * CC * HH * WW;
    for (int i = tid; i < CC * 3 * 130; i += NT) {
        int c   = i / (3 * 130);
        int rem = i % (3 * 130);
        int r   = rem / 130;
        int col = rem % 130;
        int gy = yy + r - 1; if (gy < 0) gy += HH; if (gy >= HH) gy -= HH;
        int gx = x0 + col - 1; if (gx < 0) gx += WW; if (gx >= WW) gx -= WW;
        XS[(c * 3 + r) * FST + col] = xb[(c * HH + gy) * WW + gx];
    }
    __syncthreads();

    // ---- Phase 1: perception -> F[48][128] ----
    {
        int p   = tid & 127;
        int ch0 = (tid >> 7) * 6;
        #pragma unroll
        for (int ci = 0; ci < 6; ci++) {
            int c = ch0 + ci;
            const float* r0 = &XS[(c * 3 + 0) * FST + p];
            const float* r1 = &XS[(c * 3 + 1) * FST + p];
            const float* r2 = &XS[(c * 3 + 2) * FST + p];
            float a00 = r0[0], a01 = r0[1], a02 = r0[2];
            float a10 = r1[0], a11 = r1[1], a12 = r1[2];
            float a20 = r2[0], a21 = r2[1], a22 = r2[2];
            float sx  = (a02 - a00) + 2.f * (a12 - a10) + (a22 - a20);
            float top = a00 + 2.f * a01 + a02;
            float bot = a20 + 2.f * a21 + a22;
            float sy  = bot - top;
            float lap = top + bot + 2.f * (a10 + a12) - 12.f * a11;
            int f0 = (c * 4) * FST + p;
            F[f0        ] = a11;
            F[f0 + FST  ] = sx;
            F[f0 + 2*FST] = sy;
            F[f0 + 3*FST] = lap;
        }
    }
    __syncthreads();

    // ---- Phase 2: GEMM1 in registers ----
    // thread (wrp, lh, lp): hidden rows prow..prow+11, pixels pcol..pcol+3
    const int wrp  = tid >> 5;
    const int ln   = tid & 31;
    const int lh   = ln & 7;          // 8 hidden groups
    const int lp   = ln >> 3;         // 4 pixel groups
    const int prow = lh * 12;
    const int pcol = wrp * 16 + lp * 4;

    float acc[12][4];
    #pragma unroll
    for (int i = 0; i < 12; i++) {
        float b = B1[prow + i];
        acc[i][0] = b; acc[i][1] = b; acc[i][2] = b; acc[i][3] = b;
    }

    const float* Fp  = F + pcol;
    const float* W1p = W1T + prow;
    #pragma unroll 4
    for (int k = 0; k < K4C; k++) {
        float4 fv = *(const float4*)(Fp  + k * FST);
        float4 wA = *(const float4*)(W1p + k * FCH);
        float4 wB = *(const float4*)(W1p + k * FCH + 4);
        float4 wC = *(const float4*)(W1p + k * FCH + 8);
        float wv[12];
        wv[0]=wA.x; wv[1]=wA.y; wv[2]=wA.z;  wv[3]=wA.w;
        wv[4]=wB.x; wv[5]=wB.y; wv[6]=wB.z;  wv[7]=wB.w;
        wv[8]=wC.x; wv[9]=wC.y; wv[10]=wC.z; wv[11]=wC.w;
        #pragma unroll
        for (int i = 0; i < 12; i++) {
            acc[i][0] = fmaf(wv[i], fv.x, acc[i][0]);
            acc[i][1] = fmaf(wv[i], fv.y, acc[i][1]);
            acc[i][2] = fmaf(wv[i], fv.z, acc[i][2]);
            acc[i][3] = fmaf(wv[i], fv.w, acc[i][3]);
        }
    }

    // ---- Fused GEMM2 (partial, register-resident) ----
    float yp[12][4];
    #pragma unroll
    for (int oc = 0; oc < 12; oc++) {
        yp[oc][0] = 0.f; yp[oc][1] = 0.f; yp[oc][2] = 0.f; yp[oc][3] = 0.f;
    }
    #pragma unroll
    for (int i = 0; i < 12; i++) {
        float h0 = fmaxf(acc[i][0], 0.f);
        float h1 = fmaxf(acc[i][1], 0.f);
        float h2 = fmaxf(acc[i][2], 0.f);
        float h3 = fmaxf(acc[i][3], 0.f);
        const float4* wr = (const float4*)(W2T + (prow + i) * CC);  // 48B-aligned
        float4 wa = wr[0], wb = wr[1], wc = wr[2];
        float w[12];
        w[0]=wa.x; w[1]=wa.y; w[2]=wa.z;  w[3]=wa.w;
        w[4]=wb.x; w[5]=wb.y; w[6]=wb.z;  w[7]=wb.w;
        w[8]=wc.x; w[9]=wc.y; w[10]=wc.z; w[11]=wc.w;
        #pragma unroll
        for (int oc = 0; oc < 12; oc++) {
            yp[oc][0] = fmaf(w[oc], h0, yp[oc][0]);
            yp[oc][1] = fmaf(w[oc], h1, yp[oc][1]);
            yp[oc][2] = fmaf(w[oc], h2, yp[oc][2]);
            yp[oc][3] = fmaf(w[oc], h3, yp[oc][3]);
        }
    }

    // ---- Reduce partials across the 8 lanes (lh = lane bits 0..2) ----
    #pragma unroll
    for (int oc = 0; oc < 12; oc++) {
        #pragma unroll
        for (int q = 0; q < 4; q++) {
            float v = yp[oc][q];
            v += __shfl_xor_sync(0xffffffffu, v, 1);
            v += __shfl_xor_sync(0xffffffffu, v, 2);
            v += __shfl_xor_sync(0xffffffffu, v, 4);
            yp[oc][q] = v;
        }
    }

    // ---- Epilogue: masked residual. Lane lh writes channel lh; lanes 0..3 also lh+8.
    {
        float4 rm4 = *(const float4*)(rmask + ((size_t)bb * HH + yy) * WW + x0 + pcol);
        float m0 = floorf(rm4.x + 0.5f);
        float m1 = floorf(rm4.y + 0.5f);
        float m2 = floorf(rm4.z + 0.5f);
        float m3 = floorf(rm4.w + 0.5f);

        // pass 0: channel c = lh (all 8 lanes); pass 1: c = lh + 8 (lanes lh<4)
        {
            int c = lh;
            const float* xr = &XS[(c * 3 + 1) * FST + pcol + 1];
            float4 o;
            o.x = fmaf(yp[c][0], m0, xr[0]);
            o.y = fmaf(yp[c][1], m1, xr[1]);
            o.z = fmaf(yp[c][2], m2, xr[2]);
            o.w = fmaf(yp[c][3], m3, xr[3]);
            *(float4*)(out + (((size_t)bb * CC + c) * HH + yy) * WW + x0 + pcol) = o;
        }
        if (lh < 4) {
            int c = lh + 8;
            const float* xr = &XS[(c * 3 + 1) * FST + pcol + 1];
            float4 o;
            o.x = fmaf(yp[c][0], m0, xr[0]);
            o.y = fmaf(yp[c][1], m1, xr[1]);
            o.z = fmaf(yp[c][2], m2, xr[2]);
            o.w = fmaf(yp[c][3], m3, xr[3]);
            *(float4*)(out + (((size_t)bb * CC + c) * HH + yy) * WW + x0 + pcol) = o;
        }
    }
}

extern "C" void kernel_launch(void* const* d_in, const int* in_sizes, int n_in,
                              void* d_out, int out_size)
{
    const float* x  = (const float*)d_in[0];
    const float* w1 = (const float*)d_in[1];
    const float* b1 = (const float*)d_in[2];
    const float* w2 = (const float*)d_in[3];
    const float* rm = (const float*)d_in[4];
    float* out = (float*)d_out;

    cudaFuncSetAttribute(nca_kernel, cudaFuncAttributeMaxDynamicSharedMemorySize, SMEM_BYTES);

    dim3 grid(WW / TPX, HH, 32);   // (2, 256, 32)
    nca_kernel<<<grid, NT, SMEM_BYTES>>>(x, w1, b1, w2, rm, out);
}

// round 7
// speedup vs baseline: 2.4905x; 2.4905x over previous
#include <cuda_runtime.h>
#include <cuda_bf16.h>
#include <math.h>
#include <cstdint>

// NCA update via mma.sync (HMMA) bf16 tensor cores.
// out = x + floor(rand+0.5) * (W2 @ relu(W1 @ perception(x) + b1))
// x[32,12,256,256], w1[96,48], b1[96], w2[12,96], rand[32,1,256,256].
//
// Per CTA (128 pixels of one row):
//   GEMM1: D1[128 px, 96 h] = F[128,48] . W1^T   (M=pixel, N=hidden, K=feature)
//   regs:  H = relu(D1 + b1) -> bf16 A-fragments (D-frag == A-frag layout)
//   GEMM2: D2[128 px, 16 ch] = H . W2pad^T       (K=hidden, channels 12..15 zero)
//   Y smem -> coalesced masked residual epilogue.

#define CC   12
#define FCH  96
#define HH   256
#define WW   256
#define TPX  128
#define NT   256
#define FST  132

// F row stride: 72 bf16 = 144 B = 9 x 16B -> ldmatrix conflict-free
#define FSTRIDE_BF 72
// padded strides (uint32 units) for conflict-free B-operand LDS
#define W1P_STR 104     // banks qid*8 + rid : conflict-free
#define W2P_STR 24      // banks {0,24,16,8}+rid : conflict-free

// ---- smem byte layout ----
#define SMB_F     0                        // F[128][72] bf16          = 18432
#define SMB_W1P   18432                    // [24][W1P_STR] u32        =  9984
#define SMB_W2P   (SMB_W1P + 9984)         // [48][W2P_STR] u32        =  4608
#define SMB_B1    (SMB_W2P + 4608)         // 96 f32                   =   384
#define SMB_Y     (SMB_B1 + 384)           // [12][128] f32            =  6144
#define SMB_XS    (SMB_Y + 6144)           // [12][3][132] f32         = 19008
#define SMEM_BYTES (SMB_XS + 19008)        // 58560

static __device__ __forceinline__ uint32_t smem_u32(const void* p) {
    uint32_t a;
    asm("{ .reg .u64 t; cvta.to.shared.u64 t, %1; cvt.u32.u64 %0, t; }" : "=r"(a) : "l"(p));
    return a;
}

static __device__ __forceinline__ void ldmat4(uint32_t r[4], uint32_t addr) {
    asm volatile("ldmatrix.sync.aligned.m8n8.x4.shared.b16 {%0,%1,%2,%3}, [%4];"
        : "=r"(r[0]), "=r"(r[1]), "=r"(r[2]), "=r"(r[3]) : "r"(addr));
}

static __device__ __forceinline__ void mma16816(float d[4], const uint32_t a[4],
                                                const uint32_t b0, const uint32_t b1) {
    asm volatile("mma.sync.aligned.m16n8k16.row.col.f32.bf16.bf16.f32 "
        "{%0,%1,%2,%3}, {%4,%5,%6,%7}, {%8,%9}, {%0,%1,%2,%3};"
        : "+f"(d[0]), "+f"(d[1]), "+f"(d[2]), "+f"(d[3])
        : "r"(a[0]), "r"(a[1]), "r"(a[2]), "r"(a[3]), "r"(b0), "r"(b1));
}

static __device__ __forceinline__ uint32_t packbf2(float a, float b) {
    __nv_bfloat162 p = __float22bfloat162_rn(make_float2(a, b));
    return *(uint32_t*)&p;
}

__global__ __launch_bounds__(NT, 2)
void nca_mma_kernel(const float* __restrict__ x,
                    const float* __restrict__ w1,
                    const float* __restrict__ b1,
                    const float* __restrict__ w2,
                    const float* __restrict__ rmask,
                    float* __restrict__ out)
{
    extern __shared__ char smem[];
    const uint32_t smb = smem_u32(smem);
    __nv_bfloat16* Fs  = (__nv_bfloat16*)(smem + SMB_F);
    uint32_t* W1P = (uint32_t*)(smem + SMB_W1P);
    uint32_t* W2P = (uint32_t*)(smem + SMB_W2P);
    float* B1 = (float*)(smem + SMB_B1);
    float* Y  = (float*)(smem + SMB_Y);
    float* XS = (float*)(smem + SMB_XS);

    const int tid = threadIdx.x;
    const int wid = tid >> 5;
    const int ln  = tid & 31;
    const int qid = ln & 3;     // threadID within group
    const int rid = ln >> 2;    // groupID (0..7)
    const int x0  = blockIdx.x * TPX;
    const int yy  = blockIdx.y;
    const int bb  = blockIdx.z;

    // ---- stage W1 pairs: W1P[k2][h] = (w1[h][2k2], w1[h][2k2+1]) ----
    for (int i = tid; i < 24 * FCH; i += NT) {
        int k2 = i / FCH, h = i % FCH;
        W1P[k2 * W1P_STR + h] = packbf2(w1[h * 48 + 2 * k2], w1[h * 48 + 2 * k2 + 1]);
    }
    // ---- stage W2 pairs (padded to 16 ch): W2P[h2][c] = (w2[c][2h2], w2[c][2h2+1]) ----
    for (int i = tid; i < 48 * 16; i += NT) {
        int h2 = i >> 4, c = i & 15;
        W2P[h2 * W2P_STR + c] =
            (c < CC) ? packbf2(w2[c * FCH + 2 * h2], w2[c * FCH + 2 * h2 + 1]) : 0u;
    }
    if (tid < FCH) B1[tid] = b1[tid];

    // ---- stage halo XS[12][3][130], circular pad ----
    const float* xb = x + (size_t)bb * CC * HH * WW;
    for (int i = tid; i < CC * 3 * 130; i += NT) {
        int c = i / 390, rem = i % 390, r = rem / 130, col = rem % 130;
        int gy = yy + r - 1; if (gy < 0) gy += HH; if (gy >= HH) gy -= HH;
        int gx = x0 + col - 1; if (gx < 0) gx += WW; if (gx >= WW) gx -= WW;
        XS[(c * 3 + r) * FST + col] = xb[(c * HH + gy) * WW + gx];
    }
    __syncthreads();

    // ---- perception -> F[pixel][48] bf16 (row stride 72 bf16 = 144B) ----
    {
        int p = tid & 127;
        int ch0 = (tid >> 7) * 6;
        #pragma unroll
        for (int ci = 0; ci < 6; ci++) {
            int c = ch0 + ci;
            const float* r0 = &XS[(c * 3 + 0) * FST + p];
            const float* r1 = &XS[(c * 3 + 1) * FST + p];
            const float* r2 = &XS[(c * 3 + 2) * FST + p];
            float a00 = r0[0], a01 = r0[1], a02 = r0[2];
            float a10 = r1[0], a11 = r1[1], a12 = r1[2];
            float a20 = r2[0], a21 = r2[1], a22 = r2[2];
            float sx  = (a02 - a00) + 2.f * (a12 - a10) + (a22 - a20);
            float top = a00 + 2.f * a01 + a02;
            float bot = a20 + 2.f * a21 + a22;
            float sy  = bot - top;
            float lap = top + bot + 2.f * (a10 + a12) - 12.f * a11;
            uint2 v;
            v.x = packbf2(a11, sx);
            v.y = packbf2(sy, lap);
            *(uint2*)(Fs + p * FSTRIDE_BF + c * 4) = v;
        }
    }
    __syncthreads();

    // ---- GEMM1: each warp = 16 pixels (m16), 12 hidden n8-tiles, 3 k16 steps ----
    uint32_t afrag[3][4];
    {
        int mat = ln >> 3;
        int mrow = ((mat & 1) << 3) + (ln & 7);
        uint32_t base = smb + SMB_F + (uint32_t)((wid * 16 + mrow) * 144 + ((mat >> 1) << 4));
        #pragma unroll
        for (int s = 0; s < 3; s++) ldmat4(afrag[s], base + s * 32);
    }

    float d1[12][4];
    #pragma unroll
    for (int j = 0; j < 12; j++) { d1[j][0] = d1[j][1] = d1[j][2] = d1[j][3] = 0.f; }

    #pragma unroll
    for (int j = 0; j < 12; j++) {
        int n = j * 8 + rid;
        #pragma unroll
        for (int s = 0; s < 3; s++) {
            uint32_t b0  = W1P[(s * 8 + qid) * W1P_STR + n];
            uint32_t b1v = W1P[(s * 8 + qid + 4) * W1P_STR + n];
            mma16816(d1[j], afrag[s], b0, b1v);
        }
    }

    // ---- bias + relu + pack into GEMM2 A fragments (identical frag layout) ----
    uint32_t hp0[12], hp1[12];
    #pragma unroll
    for (int j = 0; j < 12; j++) {
        int h = j * 8 + qid * 2;
        float ba = B1[h], bbv = B1[h + 1];
        hp0[j] = packbf2(fmaxf(d1[j][0] + ba, 0.f), fmaxf(d1[j][1] + bbv, 0.f));
        hp1[j] = packbf2(fmaxf(d1[j][2] + ba, 0.f), fmaxf(d1[j][3] + bbv, 0.f));
    }

    // ---- GEMM2: D2[16 px, 16 ch] = H . W2pad^T, 6 k16 steps, 2 n8 tiles ----
    float d2[2][4];
    d2[0][0] = d2[0][1] = d2[0][2] = d2[0][3] = 0.f;
    d2[1][0] = d2[1][1] = d2[1][2] = d2[1][3] = 0.f;
    #pragma unroll
    for (int s = 0; s < 6; s++) {
        uint32_t a2[4] = { hp0[2 * s], hp1[2 * s], hp0[2 * s + 1], hp1[2 * s + 1] };
        #pragma unroll
        for (int t = 0; t < 2; t++) {
            int c = t * 8 + rid;
            uint32_t b0  = W2P[(s * 8 + qid) * W2P_STR + c];
            uint32_t b1v = W2P[(s * 8 + qid + 4) * W2P_STR + c];
            mma16816(d2[t], a2, b0, b1v);
        }
    }

    // ---- store Y[ch][pixel] (channels 12..15 dropped) ----
    {
        int p0 = wid * 16 + rid;
        #pragma unroll
        for (int t = 0; t < 2; t++) {
            int ch = t * 8 + qid * 2;
            if (ch < CC) {
                Y[ch * TPX + p0]            = d2[t][0];
                Y[(ch + 1) * TPX + p0]      = d2[t][1];
                Y[ch * TPX + p0 + 8]        = d2[t][2];
                Y[(ch + 1) * TPX + p0 + 8]  = d2[t][3];
            }
        }
    }
    __syncthreads();

    // ---- epilogue: masked residual, coalesced ----
    {
        int p = tid & 127;
        int c0 = (tid >> 7) * 6;
        float rm = rmask[((size_t)bb * HH + yy) * WW + x0 + p];
        float m = floorf(rm + 0.5f);
        #pragma unroll
        for (int i = 0; i < 6; i++) {
            int c = c0 + i;
            float xc = XS[(c * 3 + 1) * FST + p + 1];
            out[(((size_t)bb * CC + c) * HH + yy) * WW + x0 + p] =
                fmaf(Y[c * TPX + p], m, xc);
        }
    }
}

extern "C" void kernel_launch(void* const* d_in, const int* in_sizes, int n_in,
                              void* d_out, int out_size)
{
    const float* x  = (const float*)d_in[0];
    const float* w1 = (const float*)d_in[1];
    const float* b1 = (const float*)d_in[2];
    const float* w2 = (const float*)d_in[3];
    const float* rm = (const float*)d_in[4];
    float* out = (float*)d_out;

    cudaFuncSetAttribute(nca_mma_kernel, cudaFuncAttributeMaxDynamicSharedMemorySize, SMEM_BYTES);

    dim3 grid(WW / TPX, HH, 32);   // (2, 256, 32)
    nca_mma_kernel<<<grid, NT, SMEM_BYTES>>>(x, w1, b1, w2, rm, out);
}

// round 9
// speedup vs baseline: 6.7512x; 2.7108x over previous
#include <cuda_runtime.h>
#include <cuda_bf16.h>
#include <math.h>
#include <cstdint>

// NCA update via mma.sync (HMMA) bf16, multi-row persistent CTA tile.
// out = x + floor(rand+0.5) * (W2 @ relu(W1 @ perception(x) + b1))
// x[32,12,256,256], w1[96,48], b1[96], w2[12,96], rand[32,1,256,256].
//
// CTA = 8 rows x 128 cols. Weights staged once; x rows in a 4-slab ring
// (each row loaded once). Per row: perception -> F, GEMM1 (HMMA), reg
// relu/pack, GEMM2 (HMMA), Y smem, masked residual epilogue.

#define CC   12
#define FCH  96
#define HH   256
#define WW   256
#define TPX  128
#define NT   256
#define RR   8          // rows per CTA

#define FSTRIDE_BF 72   // F row stride: 144B = 9 x 16B, ldmatrix conflict-free
#define W1P_STR 104     // u32 stride, banks qid*8+rid: conflict-free
#define W2P_STR 24      // u32 stride: conflict-free
#define YSTR    132     // u32 stride: banks qid*8+rid: conflict-free
#define XSTR    132     // floats per slab row

// ---- smem byte layout ----
#define SMB_F     0                        // F[128][72] bf16          = 18432
#define SMB_W1P   18432                    // [24][104] u32            =  9984
#define SMB_W2P   (SMB_W1P + 9984)         // [48][24] u32             =  4608
#define SMB_B1    (SMB_W2P + 4608)         // 96 f32                   =   384
#define SMB_Y     (SMB_B1 + 384)           // [12][132] f32            =  6336
#define SMB_XS    (SMB_Y + 6336)           // [12][4][132] f32         = 25344
#define SMEM_BYTES (SMB_XS + 25344)        // 65088

static __device__ __forceinline__ uint32_t smem_u32(const void* p) {
    uint32_t a;
    asm("{ .reg .u64 t; cvta.to.shared.u64 t, %1; cvt.u32.u64 %0, t; }" : "=r"(a) : "l"(p));
    return a;
}
static __device__ __forceinline__ void ldmat4(uint32_t r[4], uint32_t addr) {
    asm volatile("ldmatrix.sync.aligned.m8n8.x4.shared.b16 {%0,%1,%2,%3}, [%4];"
        : "=r"(r[0]), "=r"(r[1]), "=r"(r[2]), "=r"(r[3]) : "r"(addr));
}
static __device__ __forceinline__ void mma16816(float d[4], const uint32_t a[4],
                                                const uint32_t b0, const uint32_t b1) {
    asm volatile("mma.sync.aligned.m16n8k16.row.col.f32.bf16.bf16.f32 "
        "{%0,%1,%2,%3}, {%4,%5,%6,%7}, {%8,%9}, {%0,%1,%2,%3};"
        : "+f"(d[0]), "+f"(d[1]), "+f"(d[2]), "+f"(d[3])
        : "r"(a[0]), "r"(a[1]), "r"(a[2]), "r"(a[3]), "r"(b0), "r"(b1));
}
static __device__ __forceinline__ uint32_t packbf2(float a, float b) {
    __nv_bfloat162 p = __float22bfloat162_rn(make_float2(a, b));
    return *(uint32_t*)&p;
}

// load logical row ly (may be -1..256, wraps) into slab ly&3
static __device__ __forceinline__ void load_row(float* XS, const float* xb,
                                                int x0, int ly, int tid) {
    int gy = (ly + HH) & (HH - 1);
    float* dst = XS + (ly & 3) * XSTR;               // + c*4*XSTR per channel
    const float* src = xb + (size_t)gy * WW;          // + c*HH*WW per channel
    #pragma unroll
    for (int i = tid; i < CC * 128; i += NT) {
        int c = i >> 7, col = i & 127;
        dst[c * (4 * XSTR) + col + 1] = src[(size_t)c * (HH * WW) + x0 + col];
    }
    if (tid < 24) {
        int c = tid >> 1, side = tid & 1;
        int col = side ? 129 : 0;
        int gx = side ? ((x0 + 128) & (WW - 1)) : ((x0 - 1) & (WW - 1));
        dst[c * (4 * XSTR) + col] = src[(size_t)c * (HH * WW) + gx];
    }
}

__global__ __launch_bounds__(NT, 2)
void nca_mma_kernel(const float* __restrict__ x,
                    const float* __restrict__ w1,
                    const float* __restrict__ b1,
                    const float* __restrict__ w2,
                    const float* __restrict__ rmask,
                    float* __restrict__ out)
{
    extern __shared__ char smem[];
    const uint32_t smb = smem_u32(smem);
    __nv_bfloat16* Fs  = (__nv_bfloat16*)(smem + SMB_F);
    uint32_t* W1P = (uint32_t*)(smem + SMB_W1P);
    uint32_t* W2P = (uint32_t*)(smem + SMB_W2P);
    float* B1 = (float*)(smem + SMB_B1);
    float* Y  = (float*)(smem + SMB_Y);
    float* XS = (float*)(smem + SMB_XS);

    const int tid = threadIdx.x;
    const int wid = tid >> 5;
    const int ln  = tid & 31;
    const int qid = ln & 3;
    const int rid = ln >> 2;
    const int x0  = blockIdx.x * TPX;
    const int y0  = blockIdx.y * RR;
    const int bb  = blockIdx.z;

    // ---- stage weights (once per CTA, amortized over RR rows) ----
    for (int i = tid; i < 24 * FCH; i += NT) {
        int k2 = i / FCH, h = i % FCH;
        W1P[k2 * W1P_STR + h] = packbf2(w1[h * 48 + 2 * k2], w1[h * 48 + 2 * k2 + 1]);
    }
    for (int i = tid; i < 48 * 16; i += NT) {
        int h2 = i >> 4, c = i & 15;
        W2P[h2 * W2P_STR + c] =
            (c < CC) ? packbf2(w2[c * FCH + 2 * h2], w2[c * FCH + 2 * h2 + 1]) : 0u;
    }
    if (tid < FCH) B1[tid] = b1[tid];

    // ---- preload 3 slabs: rows y0-1, y0, y0+1 ----
    const float* xb = x + (size_t)bb * CC * HH * WW;
    load_row(XS, xb, x0, y0 - 1, tid);
    load_row(XS, xb, x0, y0,     tid);
    load_row(XS, xb, x0, y0 + 1, tid);
    __syncthreads();

    // hoisted ldmatrix lane address (F contents change per row, address doesn't)
    uint32_t abase;
    {
        int mat = ln >> 3;
        int mrow = ((mat & 1) << 3) + (ln & 7);
        abase = smb + SMB_F + (uint32_t)((wid * 16 + mrow) * 144 + ((mat >> 1) << 4));
    }

    for (int it = 0; it < RR; it++) {
        const int y = y0 + it;
        const int s0 = (y - 1) & 3, s1 = y & 3, s2 = (y + 1) & 3;

        // ---- perception -> F[pixel][48] bf16 ----
        {
            int p = tid & 127;
            int ch0 = (tid >> 7) * 6;
            #pragma unroll
            for (int ci = 0; ci < 6; ci++) {
                int c = ch0 + ci;
                const float* r0 = &XS[(c * 4 + s0) * XSTR + p];
                const float* r1 = &XS[(c * 4 + s1) * XSTR + p];
                const float* r2 = &XS[(c * 4 + s2) * XSTR + p];
                float a00 = r0[0], a01 = r0[1], a02 = r0[2];
                float a10 = r1[0], a11 = r1[1], a12 = r1[2];
                float a20 = r2[0], a21 = r2[1], a22 = r2[2];
                float sx  = (a02 - a00) + 2.f * (a12 - a10) + (a22 - a20);
                float top = a00 + 2.f * a01 + a02;
                float bot = a20 + 2.f * a21 + a22;
                float sy  = bot - top;
                float lap = top + bot + 2.f * (a10 + a12) - 12.f * a11;
                uint2 v;
                v.x = packbf2(a11, sx);
                v.y = packbf2(sy, lap);
                *(uint2*)(Fs + p * FSTRIDE_BF + c * 4) = v;
            }
        }
        __syncthreads();

        // ---- prefetch next row into slab (y+2)&3 (overlaps the MMAs) ----
        if (it < RR - 1) load_row(XS, xb, x0, y + 2, tid);

        // ---- GEMM1: 16 px/warp, 12 hidden n8-tiles, 3 k16 steps ----
        uint32_t afrag[3][4];
        #pragma unroll
        for (int s = 0; s < 3; s++) ldmat4(afrag[s], abase + s * 32);

        float d1[12][4];
        #pragma unroll
        for (int j = 0; j < 12; j++) { d1[j][0] = d1[j][1] = d1[j][2] = d1[j][3] = 0.f; }
        #pragma unroll
        for (int j = 0; j < 12; j++) {
            int n = j * 8 + rid;
            #pragma unroll
            for (int s = 0; s < 3; s++) {
                uint32_t b0  = W1P[(s * 8 + qid) * W1P_STR + n];
                uint32_t b1v = W1P[(s * 8 + qid + 4) * W1P_STR + n];
                mma16816(d1[j], afrag[s], b0, b1v);
            }
        }

        // ---- bias + relu + pack: D1 frag == GEMM2 A frag layout ----
        uint32_t hp0[12], hp1[12];
        #pragma unroll
        for (int j = 0; j < 12; j++) {
            int h = j * 8 + qid * 2;
            float ba = B1[h], bbv = B1[h + 1];
            hp0[j] = packbf2(fmaxf(d1[j][0] + ba, 0.f), fmaxf(d1[j][1] + bbv, 0.f));
            hp1[j] = packbf2(fmaxf(d1[j][2] + ba, 0.f), fmaxf(d1[j][3] + bbv, 0.f));
        }

        // ---- GEMM2: D2[16 px, 16 ch] = H . W2pad^T ----
        float d2[2][4];
        d2[0][0] = d2[0][1] = d2[0][2] = d2[0][3] = 0.f;
        d2[1][0] = d2[1][1] = d2[1][2] = d2[1][3] = 0.f;
        #pragma unroll
        for (int s = 0; s < 6; s++) {
            uint32_t a2[4] = { hp0[2 * s], hp1[2 * s], hp0[2 * s + 1], hp1[2 * s + 1] };
            #pragma unroll
            for (int t = 0; t < 2; t++) {
                int c = t * 8 + rid;
                uint32_t b0  = W2P[(s * 8 + qid) * W2P_STR + c];
                uint32_t b1v = W2P[(s * 8 + qid + 4) * W2P_STR + c];
                mma16816(d2[t], a2, b0, b1v);
            }
        }

        // ---- Y[ch][pixel] (stride 132: conflict-free) ----
        {
            int p0 = wid * 16 + rid;
            #pragma unroll
            for (int t = 0; t < 2; t++) {
                int ch = t * 8 + qid * 2;
                if (ch < CC) {
                    Y[ch * YSTR + p0]            = d2[t][0];
                    Y[(ch + 1) * YSTR + p0]      = d2[t][1];
                    Y[ch * YSTR + p0 + 8]        = d2[t][2];
                    Y[(ch + 1) * YSTR + p0 + 8]  = d2[t][3];
                }
            }
        }
        __syncthreads();

        // ---- epilogue: masked residual, coalesced ----
        {
            int p = tid & 127;
            int c0 = (tid >> 7) * 6;
            float rm = rmask[((size_t)bb * HH + y) * WW + x0 + p];
            float m = floorf(rm + 0.5f);
            float* orow = out + (size_t)bb * CC * HH * WW + (size_t)y * WW + x0 + p;
            #pragma unroll
            for (int i = 0; i < 6; i++) {
                int c = c0 + i;
                float xc = XS[(c * 4 + s1) * XSTR + p + 1];
                orow[(size_t)c * (HH * WW)] = fmaf(Y[c * YSTR + p], m, xc);
            }
        }
        // no trailing sync needed: next iteration's post-perception barrier
        // orders these Y/XS reads before the next Y overwrite.
    }
}

extern "C" void kernel_launch(void* const* d_in, const int* in_sizes, int n_in,
                              void* d_out, int out_size)
{
    const float* x  = (const float*)d_in[0];
    const float* w1 = (const float*)d_in[1];
    const float* b1 = (const float*)d_in[2];
    const float* w2 = (const float*)d_in[3];
    const float* rm = (const float*)d_in[4];
    float* out = (float*)d_out;

    cudaFuncSetAttribute(nca_mma_kernel, cudaFuncAttributeMaxDynamicSharedMemorySize, SMEM_BYTES);

    dim3 grid(WW / TPX, HH / RR, 32);   // (2, 32, 32)
    nca_mma_kernel<<<grid, NT, SMEM_BYTES>>>(x, w1, b1, w2, rm, out);
}

// round 10
// speedup vs baseline: 8.5075x; 1.2601x over previous
#include <cuda_runtime.h>
#include <cuda_bf16.h>
#include <math.h>
#include <cstdint>

// NCA update via mma.sync (HMMA) bf16, multi-row CTA tile, register-resident weights.
// out = x + floor(rand+0.5) * (W2 @ relu(W1 @ perception(x) + b1))
// x[32,12,256,256], w1[96,48], b1[96], w2[12,96], rand[32,1,256,256].
//
// CTA = 8 rows x 128 cols. Warp w: pixels 32*(w&3)..+31 (2 m16-tiles),
// hidden half 48*(w>>2)..+47 (6 n8-tiles). W1/W2/bias fragments live in
// registers for the whole CTA (loaded straight from gmem in frag layout).
// GEMM2 is split-k over the two hidden halves: half0 -> Y, half1 -> P,
// epilogue adds them.

#define CC   12
#define FCH  96
#define HH   256
#define WW   256
#define TPX  128
#define NT   256
#define RR   8

#define FSTRIDE_BF 72   // F row stride: 144B = 9 x 16B, ldmatrix conflict-free
#define YSTR    132     // f32 stride, conflict-free for frag stores
#define XSTR    132     // floats per slab row

// ---- smem byte layout ----
#define SMB_F     0                        // F[128][72] bf16   = 18432
#define SMB_Y     18432                    // [12][132] f32     =  6336
#define SMB_P     (SMB_Y + 6336)           // [12][132] f32     =  6336
#define SMB_XS    (SMB_P + 6336)           // [12][4][132] f32  = 25344
#define SMEM_BYTES (SMB_XS + 25344)        // 56448

static __device__ __forceinline__ uint32_t smem_u32(const void* p) {
    uint32_t a;
    asm("{ .reg .u64 t; cvta.to.shared.u64 t, %1; cvt.u32.u64 %0, t; }" : "=r"(a) : "l"(p));
    return a;
}
static __device__ __forceinline__ void ldmat4(uint32_t r[4], uint32_t addr) {
    asm volatile("ldmatrix.sync.aligned.m8n8.x4.shared.b16 {%0,%1,%2,%3}, [%4];"
        : "=r"(r[0]), "=r"(r[1]), "=r"(r[2]), "=r"(r[3]) : "r"(addr));
}
static __device__ __forceinline__ void mma16816(float d[4], const uint32_t a[4],
                                                const uint32_t b0, const uint32_t b1) {
    asm volatile("mma.sync.aligned.m16n8k16.row.col.f32.bf16.bf16.f32 "
        "{%0,%1,%2,%3}, {%4,%5,%6,%7}, {%8,%9}, {%0,%1,%2,%3};"
        : "+f"(d[0]), "+f"(d[1]), "+f"(d[2]), "+f"(d[3])
        : "r"(a[0]), "r"(a[1]), "r"(a[2]), "r"(a[3]), "r"(b0), "r"(b1));
}
static __device__ __forceinline__ uint32_t packbf2(float a, float b) {
    __nv_bfloat162 p = __float22bfloat162_rn(make_float2(a, b));
    return *(uint32_t*)&p;
}

// load logical row ly (wraps) into slab ly&3
static __device__ __forceinline__ void load_row(float* XS, const float* xb,
                                                int x0, int ly, int tid) {
    int gy = (ly + HH) & (HH - 1);
    float* dst = XS + (ly & 3) * XSTR;
    const float* src = xb + (size_t)gy * WW;
    #pragma unroll
    for (int i = tid; i < CC * 128; i += NT) {
        int c = i >> 7, col = i & 127;
        dst[c * (4 * XSTR) + col + 1] = src[(size_t)c * (HH * WW) + x0 + col];
    }
    if (tid < 24) {
        int c = tid >> 1, side = tid & 1;
        int col = side ? 129 : 0;
        int gx = side ? ((x0 + 128) & (WW - 1)) : ((x0 - 1) & (WW - 1));
        dst[c * (4 * XSTR) + col] = src[(size_t)c * (HH * WW) + gx];
    }
}

__global__ __launch_bounds__(NT, 2)
void nca_mma_kernel(const float* __restrict__ x,
                    const float* __restrict__ w1,
                    const float* __restrict__ b1,
                    const float* __restrict__ w2,
                    const float* __restrict__ rmask,
                    float* __restrict__ out)
{
    extern __shared__ char smem[];
    const uint32_t smb = smem_u32(smem);
    __nv_bfloat16* Fs = (__nv_bfloat16*)(smem + SMB_F);
    float* Y  = (float*)(smem + SMB_Y);
    float* P  = (float*)(smem + SMB_P);
    float* XS = (float*)(smem + SMB_XS);

    const int tid = threadIdx.x;
    const int wid = tid >> 5;
    const int ln  = tid & 31;
    const int qid = ln & 3;
    const int rid = ln >> 2;
    const int mh  = wid & 3;       // pixel group: px 32*mh .. +31
    const int hh  = wid >> 2;      // hidden half: 48*hh .. +47
    const int x0  = blockIdx.x * TPX;
    const int y0  = blockIdx.y * RR;
    const int bb  = blockIdx.z;

    // ---- hoist W1 B-fragments (6 n-tiles x 3 ksteps), straight from gmem ----
    // frag mapping (row.col mma): b0 = B[k=16s+2qid+{0,1}][h], b1 = +8 in k; h = 48hh+8j+rid
    uint32_t w1b0[6][3], w1b1[6][3];
    {
        const float2* w1f2 = (const float2*)w1;   // w1[h][48] -> 24 float2 per h
        #pragma unroll
        for (int j = 0; j < 6; j++) {
            int h = hh * 48 + j * 8 + rid;
            #pragma unroll
            for (int s = 0; s < 3; s++) {
                float2 p0 = w1f2[h * 24 + s * 8 + qid];
                float2 p1 = w1f2[h * 24 + s * 8 + 4 + qid];
                w1b0[j][s] = packbf2(p0.x, p0.y);
                w1b1[j][s] = packbf2(p1.x, p1.y);
            }
        }
    }
    // ---- hoist W2 B-fragments (2 n-tiles x 3 local ksteps) ----
    // c = 8t+rid (ch 12..15 are zero-padded), k local = this warp's hidden half
    uint32_t w2b0[2][3], w2b1[2][3];
    {
        const float2* w2f2 = (const float2*)w2;   // w2[c][96] -> 48 float2 per c
        #pragma unroll
        for (int t = 0; t < 2; t++) {
            int c = t * 8 + rid;
            #pragma unroll
            for (int s = 0; s < 3; s++) {
                if (c < CC) {
                    float2 p0 = w2f2[c * 48 + hh * 24 + s * 8 + qid];
                    float2 p1 = w2f2[c * 48 + hh * 24 + s * 8 + 4 + qid];
                    w2b0[t][s] = packbf2(p0.x, p0.y);
                    w2b1[t][s] = packbf2(p1.x, p1.y);
                } else { w2b0[t][s] = 0u; w2b1[t][s] = 0u; }
            }
        }
    }
    // ---- hoist biases for this warp's hidden cols ----
    float biasA[6], biasB[6];
    {
        const float2* b1f2 = (const float2*)b1;
        #pragma unroll
        for (int j = 0; j < 6; j++) {
            float2 bv = b1f2[(hh * 48 + j * 8 + qid * 2) >> 1];
            biasA[j] = bv.x; biasB[j] = bv.y;
        }
    }

    // ---- preload 3 slabs ----
    const float* xb = x + (size_t)bb * CC * HH * WW;
    load_row(XS, xb, x0, y0 - 1, tid);
    load_row(XS, xb, x0, y0,     tid);
    load_row(XS, xb, x0, y0 + 1, tid);
    __syncthreads();

    // ldmatrix lane addresses for the warp's two m16 tiles
    uint32_t abase0;
    {
        int mat = ln >> 3;
        int mrow = ((mat & 1) << 3) + (ln & 7);
        abase0 = smb + SMB_F + (uint32_t)((mh * 32 + mrow) * 144 + ((mat >> 1) << 4));
    }
    const uint32_t abase1 = abase0 + 16 * 144;

    for (int it = 0; it < RR; it++) {
        const int y = y0 + it;
        const int s0 = (y - 1) & 3, s1 = y & 3, s2 = (y + 1) & 3;

        // ---- perception -> F[pixel][48] bf16 ----
        {
            int p = tid & 127;
            int ch0 = (tid >> 7) * 6;
            #pragma unroll
            for (int ci = 0; ci < 6; ci++) {
                int c = ch0 + ci;
                const float* r0 = &XS[(c * 4 + s0) * XSTR + p];
                const float* r1 = &XS[(c * 4 + s1) * XSTR + p];
                const float* r2 = &XS[(c * 4 + s2) * XSTR + p];
                float a00 = r0[0], a01 = r0[1], a02 = r0[2];
                float a10 = r1[0], a11 = r1[1], a12 = r1[2];
                float a20 = r2[0], a21 = r2[1], a22 = r2[2];
                float sx  = (a02 - a00) + 2.f * (a12 - a10) + (a22 - a20);
                float top = a00 + 2.f * a01 + a02;
                float bot = a20 + 2.f * a21 + a22;
                float sy  = bot - top;
                float lap = top + bot + 2.f * (a10 + a12) - 12.f * a11;
                uint2 v;
                v.x = packbf2(a11, sx);
                v.y = packbf2(sy, lap);
                *(uint2*)(Fs + p * FSTRIDE_BF + c * 4) = v;
            }
        }
        __syncthreads();

        // ---- prefetch next row (overlaps MMAs) ----
        if (it < RR - 1) load_row(XS, xb, x0, y + 2, tid);

        // ---- per m16 tile: GEMM1 -> relu/pack -> GEMM2 partial -> store ----
        float* half_dst = (hh == 0) ? Y : P;
        #pragma unroll
        for (int mt = 0; mt < 2; mt++) {
            const uint32_t ab = mt ? abase1 : abase0;

            float d1[6][4];
            #pragma unroll
            for (int j = 0; j < 6; j++) { d1[j][0]=d1[j][1]=d1[j][2]=d1[j][3]=0.f; }
            #pragma unroll
            for (int s = 0; s < 3; s++) {
                uint32_t af[4];
                ldmat4(af, ab + s * 32);
                #pragma unroll
                for (int j = 0; j < 6; j++)
                    mma16816(d1[j], af, w1b0[j][s], w1b1[j][s]);
            }

            // bias + relu + pack (D1 frag == A2 frag layout within 48-block)
            uint32_t hp0[6], hp1[6];
            #pragma unroll
            for (int j = 0; j < 6; j++) {
                hp0[j] = packbf2(fmaxf(d1[j][0] + biasA[j], 0.f),
                                 fmaxf(d1[j][1] + biasB[j], 0.f));
                hp1[j] = packbf2(fmaxf(d1[j][2] + biasA[j], 0.f),
                                 fmaxf(d1[j][3] + biasB[j], 0.f));
            }

            float d2[2][4];
            d2[0][0]=d2[0][1]=d2[0][2]=d2[0][3]=0.f;
            d2[1][0]=d2[1][1]=d2[1][2]=d2[1][3]=0.f;
            #pragma unroll
            for (int s = 0; s < 3; s++) {
                uint32_t a2[4] = { hp0[2*s], hp1[2*s], hp0[2*s+1], hp1[2*s+1] };
                #pragma unroll
                for (int t = 0; t < 2; t++)
                    mma16816(d2[t], a2, w2b0[t][s], w2b1[t][s]);
            }

            // store partial to Y (hh=0) or P (hh=1)
            int p0 = mh * 32 + mt * 16 + rid;
            #pragma unroll
            for (int t = 0; t < 2; t++) {
                int ch = t * 8 + qid * 2;
                if (ch < CC) {
                    half_dst[ch * YSTR + p0]           = d2[t][0];
                    half_dst[(ch + 1) * YSTR + p0]     = d2[t][1];
                    half_dst[ch * YSTR + p0 + 8]       = d2[t][2];
                    half_dst[(ch + 1) * YSTR + p0 + 8] = d2[t][3];
                }
            }
        }
        __syncthreads();

        // ---- epilogue: y = Y + P, masked residual, coalesced ----
        {
            int p = tid & 127;
            int c0 = (tid >> 7) * 6;
            float rm = rmask[((size_t)bb * HH + y) * WW + x0 + p];
            float m = floorf(rm + 0.5f);
            float* orow = out + (size_t)bb * CC * HH * WW + (size_t)y * WW + x0 + p;
            #pragma unroll
            for (int i = 0; i < 6; i++) {
                int c = c0 + i;
                float yv = Y[c * YSTR + p] + P[c * YSTR + p];
                float xc = XS[(c * 4 + s1) * XSTR + p + 1];
                orow[(size_t)c * (HH * WW)] = fmaf(yv, m, xc);
            }
        }
        // next iteration's post-perception barrier orders these Y/P/XS reads
        // before the next Y/P overwrite.
    }
}

extern "C" void kernel_launch(void* const* d_in, const int* in_sizes, int n_in,
                              void* d_out, int out_size)
{
    const float* x  = (const float*)d_in[0];
    const float* w1 = (const float*)d_in[1];
    const float* b1 = (const float*)d_in[2];
    const float* w2 = (const float*)d_in[3];
    const float* rm = (const float*)d_in[4];
    float* out = (float*)d_out;

    cudaFuncSetAttribute(nca_mma_kernel, cudaFuncAttributeMaxDynamicSharedMemorySize, SMEM_BYTES);

    dim3 grid(WW / TPX, HH / RR, 32);   // (2, 32, 32)
    nca_mma_kernel<<<grid, NT, SMEM_BYTES>>>(x, w1, b1, w2, rm, out);
}

// round 12
// speedup vs baseline: 8.8524x; 1.0405x over previous
#include <cuda_runtime.h>
#include <cuda_bf16.h>
#include <math.h>
#include <cstdint>

// NCA update via mma.sync (HMMA) bf16, multi-row CTA tile, register weights,
// vectorized perception, feature-major F + ldmatrix.trans.
// out = x + floor(rand+0.5) * (W2 @ relu(W1 @ perception(x) + b1))

#define CC   12
#define FCH  96
#define HH   256
#define WW   256
#define TPX  128
#define NT   256
#define RR   8

#define FSTR_B  272     // F row stride bytes: 136 bf16 = 17 x 16B (ldmatrix conflict-free)
#define YSTR    132     // f32 stride
#define XSTR    132     // floats per slab row

// ---- smem byte layout ----
#define SMB_F     0                        // F[48][136] bf16  = 13056
#define SMB_Y     13056                    // [12][132] f32    =  6336
#define SMB_P     (SMB_Y + 6336)           // [12][132] f32    =  6336
#define SMB_XS    (SMB_P + 6336)           // [12][4][132] f32 = 25344
#define SMEM_BYTES (SMB_XS + 25344)        // 51072

static __device__ __forceinline__ uint32_t smem_u32(const void* p) {
    uint32_t a;
    asm("{ .reg .u64 t; cvta.to.shared.u64 t, %1; cvt.u32.u64 %0, t; }" : "=r"(a) : "l"(p));
    return a;
}
static __device__ __forceinline__ void ldmat4t(uint32_t r[4], uint32_t addr) {
    asm volatile("ldmatrix.sync.aligned.m8n8.x4.trans.shared.b16 {%0,%1,%2,%3}, [%4];"
        : "=r"(r[0]), "=r"(r[1]), "=r"(r[2]), "=r"(r[3]) : "r"(addr));
}
static __device__ __forceinline__ void mma16816(float d[4], const uint32_t a[4],
                                                const uint32_t b0, const uint32_t b1) {
    asm volatile("mma.sync.aligned.m16n8k16.row.col.f32.bf16.bf16.f32 "
        "{%0,%1,%2,%3}, {%4,%5,%6,%7}, {%8,%9}, {%0,%1,%2,%3};"
        : "+f"(d[0]), "+f"(d[1]), "+f"(d[2]), "+f"(d[3])
        : "r"(a[0]), "r"(a[1]), "r"(a[2]), "r"(a[3]), "r"(b0), "r"(b1));
}
static __device__ __forceinline__ uint32_t packbf2(float a, float b) {
    __nv_bfloat162 p = __float22bfloat162_rn(make_float2(a, b));
    return *(uint32_t*)&p;
}

// load logical row ly (wraps) into slab ly&3
static __device__ __forceinline__ void load_row(float* XS, const float* xb,
                                                int x0, int ly, int tid) {
    int gy = (ly + HH) & (HH - 1);
    float* dst = XS + (ly & 3) * XSTR;
    const float* src = xb + (size_t)gy * WW;
    #pragma unroll
    for (int i = tid; i < CC * 128; i += NT) {
        int c = i >> 7, col = i & 127;
        dst[c * (4 * XSTR) + col + 1] = src[(size_t)c * (HH * WW) + x0 + col];
    }
    if (tid < 24) {
        int c = tid >> 1, side = tid & 1;
        int col = side ? 129 : 0;
        int gx = side ? ((x0 + 128) & (WW - 1)) : ((x0 - 1) & (WW - 1));
        dst[c * (4 * XSTR) + col] = src[(size_t)c * (HH * WW) + gx];
    }
}

// perception for one (channel, 4-pixel-group) item: vector loads, feature-major F store
static __device__ __forceinline__ void perc_item(const float* XS, char* smem,
                                                 int item, int s0, int s1, int s2) {
    int c = item >> 5, g = item & 31;
    const float* b0 = &XS[(c * 4 + s0) * XSTR + 4 * g];
    const float* b1 = &XS[(c * 4 + s1) * XSTR + 4 * g];
    const float* b2 = &XS[(c * 4 + s2) * XSTR + 4 * g];
    float4 v0 = *(const float4*)b0; float2 e0 = *(const float2*)(b0 + 4);
    float4 v1 = *(const float4*)b1; float2 e1 = *(const float2*)(b1 + 4);
    float4 v2 = *(const float4*)b2; float2 e2 = *(const float2*)(b2 + 4);
    float R0[6] = {v0.x, v0.y, v0.z, v0.w, e0.x, e0.y};
    float R1[6] = {v1.x, v1.y, v1.z, v1.w, e1.x, e1.y};
    float R2[6] = {v2.x, v2.y, v2.z, v2.w, e2.x, e2.y};

    float idv[4], sxv[4], syv[4], lpv[4];
    #pragma unroll
    for (int u = 0; u < 4; u++) {
        float t0 = R0[u] + 2.f * R0[u + 1] + R0[u + 2];
        float t2 = R2[u] + 2.f * R2[u + 1] + R2[u + 2];
        idv[u] = R1[u + 1];
        sxv[u] = (R0[u + 2] - R0[u]) + 2.f * (R1[u + 2] - R1[u]) + (R2[u + 2] - R2[u]);
        syv[u] = t2 - t0;
        lpv[u] = t0 + t2 + 2.f * (R1[u] + R1[u + 2]) - 12.f * R1[u + 1];
    }
    char* fb = smem + SMB_F + (size_t)(c * 4) * FSTR_B + g * 8;
    uint2 w;
    w.x = packbf2(idv[0], idv[1]); w.y = packbf2(idv[2], idv[3]);
    *(uint2*)(fb) = w;
    w.x = packbf2(sxv[0], sxv[1]); w.y = packbf2(sxv[2], sxv[3]);
    *(uint2*)(fb + FSTR_B) = w;
    w.x = packbf2(syv[0], syv[1]); w.y = packbf2(syv[2], syv[3]);
    *(uint2*)(fb + 2 * FSTR_B) = w;
    w.x = packbf2(lpv[0], lpv[1]); w.y = packbf2(lpv[2], lpv[3]);
    *(uint2*)(fb + 3 * FSTR_B) = w;
}

__global__ __launch_bounds__(NT, 2)
void nca_mma_kernel(const float* __restrict__ x,
                    const float* __restrict__ w1,
                    const float* __restrict__ b1,
                    const float* __restrict__ w2,
                    const float* __restrict__ rmask,
                    float* __restrict__ out)
{
    extern __shared__ char smem[];
    const uint32_t smb = smem_u32(smem);
    float* Y  = (float*)(smem + SMB_Y);
    float* P  = (float*)(smem + SMB_P);
    float* XS = (float*)(smem + SMB_XS);

    const int tid = threadIdx.x;
    const int wid = tid >> 5;
    const int ln  = tid & 31;
    const int qid = ln & 3;
    const int rid = ln >> 2;
    const int mh  = wid & 3;       // pixel group: px 32*mh .. +31
    const int hh  = wid >> 2;      // hidden half: 48*hh .. +47
    const int x0  = blockIdx.x * TPX;
    const int y0  = blockIdx.y * RR;
    const int bb  = blockIdx.z;

    // ---- hoist W1 B-fragments (6 n-tiles x 3 ksteps) from gmem ----
    uint32_t w1b0[6][3], w1b1[6][3];
    {
        const float2* w1f2 = (const float2*)w1;
        #pragma unroll
        for (int j = 0; j < 6; j++) {
            int h = hh * 48 + j * 8 + rid;
            #pragma unroll
            for (int s = 0; s < 3; s++) {
                float2 p0 = w1f2[h * 24 + s * 8 + qid];
                float2 p1 = w1f2[h * 24 + s * 8 + 4 + qid];
                w1b0[j][s] = packbf2(p0.x, p0.y);
                w1b1[j][s] = packbf2(p1.x, p1.y);
            }
        }
    }
    // ---- hoist W2 B-fragments (2 n-tiles x 3 local ksteps) ----
    uint32_t w2b0[2][3], w2b1[2][3];
    {
        const float2* w2f2 = (const float2*)w2;
        #pragma unroll
        for (int t = 0; t < 2; t++) {
            int c = t * 8 + rid;
            #pragma unroll
            for (int s = 0; s < 3; s++) {
                if (c < CC) {
                    float2 p0 = w2f2[c * 48 + hh * 24 + s * 8 + qid];
                    float2 p1 = w2f2[c * 48 + hh * 24 + s * 8 + 4 + qid];
                    w2b0[t][s] = packbf2(p0.x, p0.y);
                    w2b1[t][s] = packbf2(p1.x, p1.y);
                } else { w2b0[t][s] = 0u; w2b1[t][s] = 0u; }
            }
        }
    }
    // ---- hoist biases ----
    float biasA[6], biasB[6];
    {
        const float2* b1f2 = (const float2*)b1;
        #pragma unroll
        for (int j = 0; j < 6; j++) {
            float2 bv = b1f2[(hh * 48 + j * 8 + qid * 2) >> 1];
            biasA[j] = bv.x; biasB[j] = bv.y;
        }
    }

    // ---- preload 3 slabs ----
    const float* xb = x + (size_t)bb * CC * HH * WW;
    load_row(XS, xb, x0, y0 - 1, tid);
    load_row(XS, xb, x0, y0,     tid);
    load_row(XS, xb, x0, y0 + 1, tid);
    __syncthreads();

    // ldmatrix.trans lane address: quadrant q = ln>>3, r = ln&7
    //   q0: F[k=r][m0]    q1: F[k=r][m0+8]   q2: F[k=8+r][m0]   q3: F[k=8+r][m0+8]
    uint32_t abase0;
    {
        int q = ln >> 3, r = ln & 7;
        int krow = ((q >> 1) << 3) + r;
        int pix  = mh * 32 + ((q & 1) << 3);
        abase0 = smb + SMB_F + (uint32_t)(krow * FSTR_B + pix * 2);
    }
    const uint32_t abase1 = abase0 + 32;            // +16 pixels
    const int second_item = 256 + wid * 16 + (ln & 15);  // pass-B item (ln<16)

    for (int it = 0; it < RR; it++) {
        const int y = y0 + it;
        const int s0 = (y - 1) & 3, s1 = y & 3, s2 = (y + 1) & 3;

        // ---- perception (vectorized): items 0..255 all threads, 256..383 half-warps ----
        perc_item(XS, smem, tid, s0, s1, s2);
        if (ln < 16) perc_item(XS, smem, second_item, s0, s1, s2);
        __syncthreads();

        // ---- prefetch next row (overlaps MMAs) ----
        if (it < RR - 1) load_row(XS, xb, x0, y + 2, tid);

        // ---- per m16 tile: GEMM1 -> relu/pack -> GEMM2 partial -> store ----
        float* half_dst = (hh == 0) ? Y : P;
        #pragma unroll
        for (int mt = 0; mt < 2; mt++) {
            const uint32_t ab = mt ? abase1 : abase0;

            float d1[6][4];
            #pragma unroll
            for (int j = 0; j < 6; j++) { d1[j][0]=d1[j][1]=d1[j][2]=d1[j][3]=0.f; }
            #pragma unroll
            for (int s = 0; s < 3; s++) {
                uint32_t af[4];
                ldmat4t(af, ab + s * 16 * FSTR_B);
                #pragma unroll
                for (int j = 0; j < 6; j++)
                    mma16816(d1[j], af, w1b0[j][s], w1b1[j][s]);
            }

            uint32_t hp0[6], hp1[6];
            #pragma unroll
            for (int j = 0; j < 6; j++) {
                hp0[j] = packbf2(fmaxf(d1[j][0] + biasA[j], 0.f),
                                 fmaxf(d1[j][1] + biasB[j], 0.f));
                hp1[j] = packbf2(fmaxf(d1[j][2] + biasA[j], 0.f),
                                 fmaxf(d1[j][3] + biasB[j], 0.f));
            }

            float d2[2][4];
            d2[0][0]=d2[0][1]=d2[0][2]=d2[0][3]=0.f;
            d2[1][0]=d2[1][1]=d2[1][2]=d2[1][3]=0.f;
            #pragma unroll
            for (int s = 0; s < 3; s++) {
                uint32_t a2[4] = { hp0[2*s], hp1[2*s], hp0[2*s+1], hp1[2*s+1] };
                #pragma unroll
                for (int t = 0; t < 2; t++)
                    mma16816(d2[t], a2, w2b0[t][s], w2b1[t][s]);
            }

            int p0 = mh * 32 + mt * 16 + rid;
            #pragma unroll
            for (int t = 0; t < 2; t++) {
                int ch = t * 8 + qid * 2;
                if (ch < CC) {
                    half_dst[ch * YSTR + p0]           = d2[t][0];
                    half_dst[(ch + 1) * YSTR + p0]     = d2[t][1];
                    half_dst[ch * YSTR + p0 + 8]       = d2[t][2];
                    half_dst[(ch + 1) * YSTR + p0 + 8] = d2[t][3];
                }
            }
        }
        __syncthreads();

        // ---- epilogue: y = Y + P, masked residual, coalesced ----
        {
            int p = tid & 127;
            int c0 = (tid >> 7) * 6;
            float rm = rmask[((size_t)bb * HH + y) * WW + x0 + p];
            float m = floorf(rm + 0.5f);
            float* orow = out + (size_t)bb * CC * HH * WW + (size_t)y * WW + x0 + p;
            const float* xsp = &XS[s1 * XSTR + p + 1];
            #pragma unroll
            for (int i = 0; i < 6; i++) {
                int c = c0 + i;
                float yv = Y[c * YSTR + p] + P[c * YSTR + p];
                float xc = xsp[c * (4 * XSTR)];
                orow[(size_t)c * (HH * WW)] = fmaf(yv, m, xc);
            }
        }
        // next iteration's post-perception barrier orders these Y/P/XS reads
        // before the next overwrite.
    }
}

extern "C" void kernel_launch(void* const* d_in, const int* in_sizes, int n_in,
                              void* d_out, int out_size)
{
    const float* x  = (const float*)d_in[0];
    const float* w1 = (const float*)d_in[1];
    const float* b1 = (const float*)d_in[2];
    const float* w2 = (const float*)d_in[3];
    const float* rm = (const float*)d_in[4];
    float* out = (float*)d_out;

    cudaFuncSetAttribute(nca_mma_kernel, cudaFuncAttributeMaxDynamicSharedMemorySize, SMEM_BYTES);

    dim3 grid(WW / TPX, HH / RR, 32);   // (2, 32, 32)
    nca_mma_kernel<<<grid, NT, SMEM_BYTES>>>(x, w1, b1, w2, rm, out);
}